// round 13
// baseline (speedup 1.0000x reference)
#include <cuda_runtime.h>
#include <cstdint>

#define NB      8
#define NPER    4096
#define NTOT    32768
#define KNN     16
#define DIN     32
#define DH      64
#define DOUT    128

typedef unsigned long long u64;

// ---------------- device scratch ----------------
static __device__ int    g_nbr[NTOT * KNN];
static __device__ float  g_xw [NTOT * DH];
static __device__ float  g_agg[NTOT * DH];
static __device__ float4 g_posS[NTOT];   // x-sorted per graph: (x,y,z,sq)
static __device__ int    g_sidx[NTOT];   // sorted rank -> original local idx

// ---------------- exact-arithmetic helpers (match XLA fp32) ----------------
__device__ __forceinline__ float sq3_exact(float x, float y, float z) {
    return __fadd_rn(__fadd_rn(__fmul_rn(x, x), __fmul_rn(y, y)), __fmul_rn(z, z));
}
__device__ __forceinline__ float dist_exact(float qx, float qy, float qz, float qsq,
                                            float cx, float cy, float cz, float csq) {
    float dot = __fmaf_rn(qz, cz, __fmaf_rn(qy, cy, __fmul_rn(qx, cx)));
    return __fsub_rn(__fadd_rn(qsq, csq), __fmul_rn(2.0f, dot));
}

// ---------------- packed fp32x2 FMA (Blackwell FFMA2; per-element rn) ----------------
__device__ __forceinline__ void fma2(u64& acc, u64 a2, u64 b2) {
    asm("fma.rn.f32x2 %0, %1, %2, %0;" : "+l"(acc) : "l"(a2), "l"(b2));
}
__device__ __forceinline__ u64 pack_dup(float a) {
    u64 v; asm("mov.b64 %0, {%1, %1};" : "=l"(v) : "f"(a)); return v;
}
__device__ __forceinline__ float2 unpack2(u64 v) {
    float2 f; asm("mov.b64 {%0, %1}, %2;" : "=f"(f.x), "=f"(f.y) : "l"(v)); return f;
}

// float bits -> order-preserving unsigned
__device__ __forceinline__ unsigned int ordbits(unsigned int b) {
    return (b & 0x80000000u) ? ~b : (b | 0x80000000u);
}

// sorted-ascending insert of packed (dist,idx) key into 16-deep register list
__device__ __forceinline__ void insk16(u64 k, u64 (&K)[16]) {
#pragma unroll
    for (int s = 0; s < 16; ++s) {
        bool p = k < K[s];
        u64 lo = p ? k : K[s];
        u64 hi = p ? K[s] : k;
        K[s] = lo; k = hi;
    }
}

// ---------------- K0: per-graph bitonic sort by x ----------------
// grid = 8 (one per graph), 1024 thr; key = ordbits(x)<<32 | local_idx (unique).
__global__ void __launch_bounds__(1024) sort_kernel(const float* __restrict__ pos) {
    __shared__ u64 keys[NPER];   // 32KB
    int g = blockIdx.x, t = threadIdx.x;
    int cbase = g * NPER;
    for (int i = t; i < NPER; i += 1024) {
        float x = pos[(size_t)(cbase + i) * 3];
        keys[i] = ((u64)ordbits(__float_as_uint(x)) << 32) | (unsigned)i;
    }
    __syncthreads();
    for (int k = 2; k <= NPER; k <<= 1) {
        for (int j = k >> 1; j > 0; j >>= 1) {
            for (int i = t; i < NPER; i += 1024) {
                int l = i ^ j;
                if (l > i) {
                    u64 a = keys[i], b = keys[l];
                    bool up = ((i & k) == 0);
                    if ((a > b) == up) { keys[i] = b; keys[l] = a; }
                }
            }
            __syncthreads();
        }
    }
    for (int i = t; i < NPER; i += 1024) {
        int oi = (int)(keys[i] & 0xFFFFFFFFull);
        float px = pos[(size_t)(cbase + oi) * 3 + 0];
        float py = pos[(size_t)(cbase + oi) * 3 + 1];
        float pz = pos[(size_t)(cbase + oi) * 3 + 2];
        g_posS[cbase + i] = make_float4(px, py, pz, sq3_exact(px, py, pz));
        g_sidx[cbase + i] = oi;
    }
}

// ---------------- K1: windowed exact KNN over x-sorted points ----------------
// grid = 256, 128 thr (4 warps). Warp = 32 consecutive sorted queries. Scans
// candidates outward from its rank block in groups of 8 (broadcast loads),
// branch-free predicated append (R12 machinery), warp-vote drains, and a
// PROVABLY-SAFE stop: direction ends when all lanes have boundary dx^2 >
// worstd + MARGIN (dist >= dx^2 - eps, eps << MARGIN). Keys = (dist bits,
// ORIGINAL local idx) -> selection set + tie-break identical to reference.
#define KBUF   15
#define MARGIN 2e-3f
__global__ void __launch_bounds__(128) knn_kernel() {
    __shared__ uint2 sbuf[128 * KBUF];   // 15KB

    int t     = threadIdx.x;
    int lane  = t & 31;
    int gwarp = blockIdx.x * 4 + (t >> 5);    // 0..1023
    int graph = gwarp >> 7;                   // 128 warps per graph
    int base  = graph * NPER + (gwarp & 127) * 32;
    int gs    = graph * NPER, ge = gs + NPER;
    int r     = base + lane;

    float4 qv = g_posS[r];
    float qx = qv.x, qy = qv.y, qz = qv.z, qsq = qv.w;
    int oi_q = g_sidx[r];

    u64 K[16];
#pragma unroll
    for (int s = 0; s < 16; ++s) K[s] = ~0ull;
    float worstd = __int_as_float(0x7f800000);   // +inf -> append-all until full
    int cnt = 0;
    uint2* mybuf = &sbuf[t * KBUF];

    // ---- RIGHT scan: groups [c0, c0+7] ascending from base ----
#pragma unroll 1
    for (int c0 = base; c0 < ge; c0 += 8) {
        float xlast = 0.f;
#pragma unroll
        for (int u = 0; u < 8; ++u) {
            int c  = c0 + u;
            int cc = min(c, ge - 1);
            float4 cv = __ldg(&g_posS[cc]);
            unsigned oc = (unsigned)__ldg(&g_sidx[cc]);
            float d = dist_exact(qx, qy, qz, qsq, cv.x, cv.y, cv.z, cv.w);
            mybuf[cnt] = make_uint2(__float_as_uint(d), oc);
            cnt += (c < ge && !(d > worstd)) ? 1 : 0;
            if (u == 7) xlast = cv.x;
        }
        if (__any_sync(0xffffffffu, cnt >= KBUF - 8)) {
            for (int k = 0; k < cnt; ++k) {
                uint2 e = mybuf[k];
                u64 key = ((u64)ordbits(e.x) << 16) | e.y;
                if (key < K[15]) insk16(key, K);
            }
            cnt = 0;
            unsigned int o = (unsigned int)(K[15] >> 16);
            unsigned int b = (o & 0x80000000u) ? (o & 0x7FFFFFFFu) : ~o;
            worstd = __uint_as_float(b);         // NaN while list not full (safe)
        }
        float dxr = xlast - qx;                  // >= 0 for all future right cands
        if (__all_sync(0xffffffffu, dxr * dxr > worstd + MARGIN)) break;
    }

    // ---- LEFT scan: groups [c0, c0+7] descending windows below base ----
#pragma unroll 1
    for (int c0 = base - 8; c0 >= gs - 7; c0 -= 8) {
        float xfirst = 0.f;
#pragma unroll
        for (int u = 0; u < 8; ++u) {
            int c  = c0 + u;
            int cc = max(c, gs);
            float4 cv = __ldg(&g_posS[cc]);
            unsigned oc = (unsigned)__ldg(&g_sidx[cc]);
            float d = dist_exact(qx, qy, qz, qsq, cv.x, cv.y, cv.z, cv.w);
            mybuf[cnt] = make_uint2(__float_as_uint(d), oc);
            cnt += (c >= gs && !(d > worstd)) ? 1 : 0;
            if (u == 0) xfirst = cv.x;
        }
        if (__any_sync(0xffffffffu, cnt >= KBUF - 8)) {
            for (int k = 0; k < cnt; ++k) {
                uint2 e = mybuf[k];
                u64 key = ((u64)ordbits(e.x) << 16) | e.y;
                if (key < K[15]) insk16(key, K);
            }
            cnt = 0;
            unsigned int o = (unsigned int)(K[15] >> 16);
            unsigned int b = (o & 0x80000000u) ? (o & 0x7FFFFFFFu) : ~o;
            worstd = __uint_as_float(b);
        }
        float dxl = qx - xfirst;                 // >= 0 for all future left cands
        if (__all_sync(0xffffffffu, dxl * dxl > worstd + MARGIN)) break;
    }

    // final drain
    for (int k = 0; k < cnt; ++k) {
        uint2 e = mybuf[k];
        u64 key = ((u64)ordbits(e.x) << 16) | e.y;
        if (key < K[15]) insk16(key, K);
    }

#pragma unroll
    for (int s = 0; s < 16; ++s)
        g_nbr[(size_t)(gs + oi_q) * KNN + s] = gs + (int)(K[s] & 0xFFFFull);
}

// ---------------- K2: xw = x @ fW1[0:32,:] + fb1 ; zero g_agg (FFMA2) ----------------
__global__ void __launch_bounds__(256) xw_kernel(const float* __restrict__ x,
                                                 const float* __restrict__ fW1,
                                                 const float* __restrict__ fb1) {
    __shared__ float sX[32 * 128];   // [i][n]
    __shared__ float sW[32 * 64];    // [i][j]
    __shared__ float sB[64];
    int t = threadIdx.x, nb = blockIdx.x * 128;
    {
        int n = t & 127, ih = (t >> 7) * 16;
        const float4* xr = (const float4*)(x + (size_t)(nb + n) * DIN + ih);
#pragma unroll
        for (int c4 = 0; c4 < 4; ++c4) {
            float4 v = xr[c4]; int i = ih + c4 * 4;
            sX[(i + 0) * 128 + n] = v.x; sX[(i + 1) * 128 + n] = v.y;
            sX[(i + 2) * 128 + n] = v.z; sX[(i + 3) * 128 + n] = v.w;
        }
    }
    for (int idx = t * 4; idx < 2048; idx += 1024)
        *(float4*)&sW[idx] = *(const float4*)&fW1[idx];
    if (t < 64) sB[t] = fb1[t];
    __syncthreads();

    int n0 = (t & 31) * 4, j0 = (t >> 5) * 8;
    u64 acc2[4][4];
#pragma unroll
    for (int r = 0; r < 4; ++r)
#pragma unroll
        for (int c = 0; c < 4; ++c) acc2[r][c] = 0ull;
#pragma unroll
    for (int i = 0; i < 32; ++i) {
        float4 a = *(float4*)&sX[i * 128 + n0];
        ulonglong2 bb0 = *(ulonglong2*)&sW[i * 64 + j0];
        ulonglong2 bb1 = *(ulonglong2*)&sW[i * 64 + j0 + 4];
        u64 b2[4] = {bb0.x, bb0.y, bb1.x, bb1.y};
        u64 ar[4] = {pack_dup(a.x), pack_dup(a.y), pack_dup(a.z), pack_dup(a.w)};
#pragma unroll
        for (int r = 0; r < 4; ++r)
#pragma unroll
            for (int c = 0; c < 4; ++c) fma2(acc2[r][c], ar[r], b2[c]);
    }
#pragma unroll
    for (int r = 0; r < 4; ++r) {
        int n = nb + n0 + r;
        float2 v0 = unpack2(acc2[r][0]), v1 = unpack2(acc2[r][1]);
        float2 v2 = unpack2(acc2[r][2]), v3 = unpack2(acc2[r][3]);
        float4 o0 = make_float4(v0.x + sB[j0 + 0], v0.y + sB[j0 + 1],
                                v1.x + sB[j0 + 2], v1.y + sB[j0 + 3]);
        float4 o1 = make_float4(v2.x + sB[j0 + 4], v2.y + sB[j0 + 5],
                                v3.x + sB[j0 + 6], v3.y + sB[j0 + 7]);
        *(float4*)&g_xw[(size_t)n * DH + j0]     = o0;
        *(float4*)&g_xw[(size_t)n * DH + j0 + 4] = o1;
        float4 z4 = make_float4(0.f, 0.f, 0.f, 0.f);
        *(float4*)&g_agg[(size_t)n * DH + j0]     = z4;
        *(float4*)&g_agg[(size_t)n * DH + j0 + 4] = z4;
    }
}

// ---------------- K3: edge MLP + atomic segment max (FFMA2 phase 2) ----------------
__global__ void __launch_bounds__(128) edge_kernel(const float* __restrict__ pos,
                                                   const float* __restrict__ fW1,
                                                   const float* __restrict__ fW2,
                                                   const float* __restrict__ fb2) {
    __shared__ float sW2[64 * 64];   // [i][j]
    __shared__ float sH [64 * 64];   // [i][e]
    __shared__ float sXW[4 * 64];
    __shared__ float sWp[3 * 64];
    __shared__ float sB2[64];
    __shared__ int   sNbr[64];
    __shared__ float sPq[12];

    int t = threadIdx.x, q0 = blockIdx.x * 4;
    for (int idx = t * 4; idx < 4096; idx += 512)
        *(float4*)&sW2[idx] = *(const float4*)&fW2[idx];
    for (int idx = t; idx < 256; idx += 128)
        sXW[idx] = g_xw[(size_t)q0 * DH + idx];
    for (int idx = t; idx < 192; idx += 128)
        sWp[idx] = fW1[32 * 64 + idx];               // rows 32..34 (pos part)
    if (t < 64)  { sB2[t] = fb2[t]; sNbr[t] = g_nbr[q0 * KNN + t]; }
    if (t < 12)  sPq[t] = pos[q0 * 3 + t];
    __syncthreads();

    // phase 1: sH[i][e] = relu(xw[q][i] + dpos . Wp[:,i])
    {
        int e = t & 63, i0 = (t >> 6) * 32, ql = e >> 4;
        int nbr = sNbr[e];
        float dx = sPq[ql * 3 + 0] - pos[nbr * 3 + 0];
        float dy = sPq[ql * 3 + 1] - pos[nbr * 3 + 1];
        float dz = sPq[ql * 3 + 2] - pos[nbr * 3 + 2];
#pragma unroll
        for (int ib = 0; ib < 32; ib += 4) {
            int i = i0 + ib;
            float4 xw = *(float4*)&sXW[ql * 64 + i];
            float4 w0 = *(float4*)&sWp[0 * 64 + i];
            float4 w1 = *(float4*)&sWp[1 * 64 + i];
            float4 w2 = *(float4*)&sWp[2 * 64 + i];
            sH[(i + 0) * 64 + e] = fmaxf(fmaf(dz, w2.x, fmaf(dy, w1.x, fmaf(dx, w0.x, xw.x))), 0.f);
            sH[(i + 1) * 64 + e] = fmaxf(fmaf(dz, w2.y, fmaf(dy, w1.y, fmaf(dx, w0.y, xw.y))), 0.f);
            sH[(i + 2) * 64 + e] = fmaxf(fmaf(dz, w2.z, fmaf(dy, w1.z, fmaf(dx, w0.z, xw.z))), 0.f);
            sH[(i + 3) * 64 + e] = fmaxf(fmaf(dz, w2.w, fmaf(dy, w1.w, fmaf(dx, w0.w, xw.w))), 0.f);
        }
    }
    __syncthreads();

    // phase 2: h2 = relu(h1 @ W2 + b2) via FFMA2, atomicMax into g_agg[nbr]
    int e0 = (t & 15) * 4, j0 = (t >> 4) * 8;
    u64 acc2[4][4];
#pragma unroll
    for (int r = 0; r < 4; ++r)
#pragma unroll
        for (int c = 0; c < 4; ++c) acc2[r][c] = 0ull;
#pragma unroll
    for (int i = 0; i < 64; ++i) {
        float4 a = *(float4*)&sH[i * 64 + e0];
        ulonglong2 bb0 = *(ulonglong2*)&sW2[i * 64 + j0];
        ulonglong2 bb1 = *(ulonglong2*)&sW2[i * 64 + j0 + 4];
        u64 b2[4] = {bb0.x, bb0.y, bb1.x, bb1.y};
        u64 ar[4] = {pack_dup(a.x), pack_dup(a.y), pack_dup(a.z), pack_dup(a.w)};
#pragma unroll
        for (int r = 0; r < 4; ++r)
#pragma unroll
            for (int c = 0; c < 4; ++c) fma2(acc2[r][c], ar[r], b2[c]);
    }
#pragma unroll
    for (int r = 0; r < 4; ++r) {
        int nbr = sNbr[e0 + r];
        int* dst = (int*)&g_agg[(size_t)nbr * DH + j0];
#pragma unroll
        for (int c = 0; c < 4; ++c) {
            float2 v = unpack2(acc2[r][c]);
            float va = fmaxf(v.x + sB2[j0 + 2 * c + 0], 0.f);
            float vb = fmaxf(v.y + sB2[j0 + 2 * c + 1], 0.f);
            if (va > 0.f) atomicMax(&dst[2 * c + 0], __float_as_int(va));
            if (vb > 0.f) atomicMax(&dst[2 * c + 1], __float_as_int(vb));
        }
    }
}

// ---------------- K4: out = relu(agg @ gW + gb) (FFMA2) ----------------
__global__ void __launch_bounds__(256) out_kernel(const float* __restrict__ gW,
                                                  const float* __restrict__ gb,
                                                  float* __restrict__ out) {
    __shared__ float sA[64 * 64];    // [i][n]
    __shared__ float sW[64 * 128];   // [i][j]
    __shared__ float sB[128];
    int t = threadIdx.x, nb = blockIdx.x * 64;
    {
        int n = t & 63, ih = (t >> 6) * 16;
        const float4* ar = (const float4*)(g_agg + (size_t)(nb + n) * DH + ih);
#pragma unroll
        for (int c4 = 0; c4 < 4; ++c4) {
            float4 v = ar[c4]; int i = ih + c4 * 4;
            sA[(i + 0) * 64 + n] = v.x; sA[(i + 1) * 64 + n] = v.y;
            sA[(i + 2) * 64 + n] = v.z; sA[(i + 3) * 64 + n] = v.w;
        }
    }
    for (int idx = t * 4; idx < 8192; idx += 1024)
        *(float4*)&sW[idx] = *(const float4*)&gW[idx];
    if (t < 128) sB[t] = gb[t];
    __syncthreads();

    int n0 = (t & 15) * 4, j0 = (t >> 4) * 8;
    u64 acc2[4][4];
#pragma unroll
    for (int r = 0; r < 4; ++r)
#pragma unroll
        for (int c = 0; c < 4; ++c) acc2[r][c] = 0ull;
#pragma unroll
    for (int i = 0; i < 64; ++i) {
        float4 a = *(float4*)&sA[i * 64 + n0];
        ulonglong2 bb0 = *(ulonglong2*)&sW[i * 128 + j0];
        ulonglong2 bb1 = *(ulonglong2*)&sW[i * 128 + j0 + 4];
        u64 b2[4] = {bb0.x, bb0.y, bb1.x, bb1.y};
        u64 ar[4] = {pack_dup(a.x), pack_dup(a.y), pack_dup(a.z), pack_dup(a.w)};
#pragma unroll
        for (int r = 0; r < 4; ++r)
#pragma unroll
            for (int c = 0; c < 4; ++c) fma2(acc2[r][c], ar[r], b2[c]);
    }
#pragma unroll
    for (int r = 0; r < 4; ++r) {
        int n = nb + n0 + r;
        float2 v0 = unpack2(acc2[r][0]), v1 = unpack2(acc2[r][1]);
        float2 v2 = unpack2(acc2[r][2]), v3 = unpack2(acc2[r][3]);
        float4 o0 = make_float4(fmaxf(v0.x + sB[j0 + 0], 0.f), fmaxf(v0.y + sB[j0 + 1], 0.f),
                                fmaxf(v1.x + sB[j0 + 2], 0.f), fmaxf(v1.y + sB[j0 + 3], 0.f));
        float4 o1 = make_float4(fmaxf(v2.x + sB[j0 + 4], 0.f), fmaxf(v2.y + sB[j0 + 5], 0.f),
                                fmaxf(v3.x + sB[j0 + 6], 0.f), fmaxf(v3.y + sB[j0 + 7], 0.f));
        *(float4*)&out[(size_t)n * DOUT + j0]     = o0;
        *(float4*)&out[(size_t)n * DOUT + j0 + 4] = o1;
    }
}

// ---------------- K5: append pos (+ batch as float) if tuple flattened ----------------
__global__ void __launch_bounds__(256) tail_kernel(const float* __restrict__ pos,
                                                   float* __restrict__ out,
                                                   int out_size) {
    int idx = blockIdx.x * blockDim.x + threadIdx.x;
    const int base = NTOT * DOUT;
    int pos_n = NTOT * 3;
    if (out_size >= base + pos_n && idx < pos_n)
        out[base + idx] = pos[idx];
    if (out_size >= base + pos_n + NTOT && idx < NTOT)
        out[base + pos_n + idx] = (float)(idx / NPER);
}

extern "C" void kernel_launch(void* const* d_in, const int* in_sizes, int n_in,
                              void* d_out, int out_size) {
    const float* x    = (const float*)d_in[0];
    const float* pos  = (const float*)d_in[1];
    // d_in[2] = batch (int32): deterministic repeat(arange(B), NPER)
    const float* fW1  = (const float*)d_in[3];
    const float* fb1  = (const float*)d_in[4];
    const float* fW2  = (const float*)d_in[5];
    const float* fb2  = (const float*)d_in[6];
    const float* gW   = (const float*)d_in[7];
    const float* gb   = (const float*)d_in[8];
    float* out = (float*)d_out;

    sort_kernel<<<NB, 1024>>>(pos);
    knn_kernel<<<256, 128>>>();
    xw_kernel<<<256, 256>>>(x, fW1, fb1);
    edge_kernel<<<8192, 128>>>(pos, fW1, fW2, fb2);
    out_kernel<<<512, 256>>>(gW, gb, out);
    if (out_size > NTOT * DOUT)
        tail_kernel<<<512, 256>>>(pos, out, out_size);
}

// round 14
// speedup vs baseline: 1.4409x; 1.4409x over previous
#include <cuda_runtime.h>
#include <cstdint>

#define NB      8
#define NPER    4096
#define NTOT    32768
#define KNN     16
#define DIN     32
#define DH      64
#define DOUT    128

typedef unsigned long long u64;

// ---------------- device scratch ----------------
static __device__ int   g_nbr[NTOT * KNN];
static __device__ float g_xw [NTOT * DH];
static __device__ float g_agg[NTOT * DH];

// ---------------- exact-arithmetic helpers (match XLA fp32) ----------------
__device__ __forceinline__ float sq3_exact(float x, float y, float z) {
    return __fadd_rn(__fadd_rn(__fmul_rn(x, x), __fmul_rn(y, y)), __fmul_rn(z, z));
}
__device__ __forceinline__ float dist_exact(float qx, float qy, float qz, float qsq,
                                            float cx, float cy, float cz, float csq) {
    float dot = __fmaf_rn(qz, cz, __fmaf_rn(qy, cy, __fmul_rn(qx, cx)));
    return __fsub_rn(__fadd_rn(qsq, csq), __fmul_rn(2.0f, dot));
}

// ---------------- packed fp32x2 FMA (Blackwell FFMA2; per-element rn) ----------------
__device__ __forceinline__ void fma2(u64& acc, u64 a2, u64 b2) {
    asm("fma.rn.f32x2 %0, %1, %2, %0;" : "+l"(acc) : "l"(a2), "l"(b2));
}
__device__ __forceinline__ u64 pack_dup(float a) {
    u64 v; asm("mov.b64 %0, {%1, %1};" : "=l"(v) : "f"(a)); return v;
}
__device__ __forceinline__ float2 unpack2(u64 v) {
    float2 f; asm("mov.b64 {%0, %1}, %2;" : "=f"(f.x), "=f"(f.y) : "l"(v)); return f;
}

// float bits -> order-preserving unsigned
__device__ __forceinline__ unsigned int ordbits(unsigned int b) {
    return (b & 0x80000000u) ? ~b : (b | 0x80000000u);
}

// sorted-ascending insert of packed (dist,idx) key into 16-deep register list
__device__ __forceinline__ void insk16(u64 k, u64 (&K)[16]) {
#pragma unroll
    for (int s = 0; s < 16; ++s) {
        bool p = k < K[s];
        u64 lo = p ? k : K[s];
        u64 hi = p ? K[s] : k;
        K[s] = lo; k = hi;
    }
}

// ---------------- K1: per-graph brute-force KNN, BRANCH-FREE (R12 exact) ----------------
#define KBUF 15
__global__ void __launch_bounds__(256) knn_kernel(const float* __restrict__ pos) {
    __shared__ float4 sc[1024];                 // staged candidates (x,y,z,sq) 16KB
    __shared__ uint2  sbuf[256 * KBUF];         // per-lane append buffers      30KB

    int graph = blockIdx.x >> 4;
    int q     = graph * NPER + (blockIdx.x & 15) * 256 + threadIdx.x;
    int cbase = graph * NPER;

    float qx = pos[q * 3 + 0], qy = pos[q * 3 + 1], qz = pos[q * 3 + 2];
    float qsq = sq3_exact(qx, qy, qz);

    u64 K[16];
#pragma unroll
    for (int s = 0; s < 16; ++s) K[s] = ~0ull;
    float worstd = __int_as_float(0x7f800000);   // +inf -> append-all until full
    int cnt = 0;
    uint2* mybuf = &sbuf[threadIdx.x * KBUF];

#pragma unroll 1
    for (int chunk = 0; chunk < 4; ++chunk) {
#pragma unroll
        for (int u = 0; u < 4; ++u) {
            int li = threadIdx.x + u * 256;
            int gi = cbase + chunk * 1024 + li;
            float x = pos[gi * 3 + 0], y = pos[gi * 3 + 1], z = pos[gi * 3 + 2];
            sc[li] = make_float4(x, y, z, sq3_exact(x, y, z));
        }
        __syncthreads();

#pragma unroll 1
        for (int j = 0; j < 1024; j += 8) {
#pragma unroll
            for (int u = 0; u < 8; ++u) {
                float4 c = sc[j + u];
                float d = dist_exact(qx, qy, qz, qsq, c.x, c.y, c.z, c.w);
                mybuf[cnt] = make_uint2(__float_as_uint(d),
                                        (unsigned)(chunk * 1024 + j + u));
                cnt += !(d > worstd) ? 1 : 0;    // NaN/inf worstd -> take
            }
            if (__any_sync(0xffffffffu, cnt >= KBUF - 8)) {   // warp-uniform
                for (int k = 0; k < cnt; ++k) {
                    uint2 e = mybuf[k];
                    u64 key = ((u64)ordbits(e.x) << 16) | e.y;
                    if (key < K[15]) insk16(key, K);
                }
                cnt = 0;
                unsigned int o = (unsigned int)(K[15] >> 16);
                unsigned int b = (o & 0x80000000u) ? (o & 0x7FFFFFFFu) : ~o;
                worstd = __uint_as_float(b);     // NaN while list not full (safe)
            }
        }
        __syncthreads();
    }

    for (int k = 0; k < cnt; ++k) {
        uint2 e = mybuf[k];
        u64 key = ((u64)ordbits(e.x) << 16) | e.y;
        if (key < K[15]) insk16(key, K);
    }

#pragma unroll
    for (int s = 0; s < 16; ++s)
        g_nbr[q * KNN + s] = cbase + (int)(K[s] & 0xFFFFull);
}

// ---------------- K2: xw = x @ fW1[0:32,:] + fb1 ; zero g_agg (FFMA2) ----------------
__global__ void __launch_bounds__(256) xw_kernel(const float* __restrict__ x,
                                                 const float* __restrict__ fW1,
                                                 const float* __restrict__ fb1) {
    __shared__ float sX[32 * 128];   // [i][n]
    __shared__ float sW[32 * 64];    // [i][j]
    __shared__ float sB[64];
    int t = threadIdx.x, nb = blockIdx.x * 128;
    {
        int n = t & 127, ih = (t >> 7) * 16;
        const float4* xr = (const float4*)(x + (size_t)(nb + n) * DIN + ih);
#pragma unroll
        for (int c4 = 0; c4 < 4; ++c4) {
            float4 v = xr[c4]; int i = ih + c4 * 4;
            sX[(i + 0) * 128 + n] = v.x; sX[(i + 1) * 128 + n] = v.y;
            sX[(i + 2) * 128 + n] = v.z; sX[(i + 3) * 128 + n] = v.w;
        }
    }
    for (int idx = t * 4; idx < 2048; idx += 1024)
        *(float4*)&sW[idx] = *(const float4*)&fW1[idx];
    if (t < 64) sB[t] = fb1[t];
    __syncthreads();

    int n0 = (t & 31) * 4, j0 = (t >> 5) * 8;
    u64 acc2[4][4];
#pragma unroll
    for (int r = 0; r < 4; ++r)
#pragma unroll
        for (int c = 0; c < 4; ++c) acc2[r][c] = 0ull;
#pragma unroll
    for (int i = 0; i < 32; ++i) {
        float4 a = *(float4*)&sX[i * 128 + n0];
        ulonglong2 bb0 = *(ulonglong2*)&sW[i * 64 + j0];
        ulonglong2 bb1 = *(ulonglong2*)&sW[i * 64 + j0 + 4];
        u64 b2[4] = {bb0.x, bb0.y, bb1.x, bb1.y};
        u64 ar[4] = {pack_dup(a.x), pack_dup(a.y), pack_dup(a.z), pack_dup(a.w)};
#pragma unroll
        for (int r = 0; r < 4; ++r)
#pragma unroll
            for (int c = 0; c < 4; ++c) fma2(acc2[r][c], ar[r], b2[c]);
    }
#pragma unroll
    for (int r = 0; r < 4; ++r) {
        int n = nb + n0 + r;
        float2 v0 = unpack2(acc2[r][0]), v1 = unpack2(acc2[r][1]);
        float2 v2 = unpack2(acc2[r][2]), v3 = unpack2(acc2[r][3]);
        float4 o0 = make_float4(v0.x + sB[j0 + 0], v0.y + sB[j0 + 1],
                                v1.x + sB[j0 + 2], v1.y + sB[j0 + 3]);
        float4 o1 = make_float4(v2.x + sB[j0 + 4], v2.y + sB[j0 + 5],
                                v3.x + sB[j0 + 6], v3.y + sB[j0 + 7]);
        *(float4*)&g_xw[(size_t)n * DH + j0]     = o0;
        *(float4*)&g_xw[(size_t)n * DH + j0 + 4] = o1;
        float4 z4 = make_float4(0.f, 0.f, 0.f, 0.f);
        *(float4*)&g_agg[(size_t)n * DH + j0]     = z4;
        *(float4*)&g_agg[(size_t)n * DH + j0 + 4] = z4;
    }
}

// ---------------- K3: edge MLP + atomic segment max, BIG TILES ----------------
// block = 16 queries = 256 edges, 128 thr, grid = 2048. Dynamic smem:
//   [0, 4096)            sW2  [i][j]   16KB
//   [4096, 4096+16384)   sH   [i][e]   64KB (row stride 256)
// Phase-2 thread tile = 8 edges x 16 j (0.75 B LDS per scalar FMA, 2x less
// smem traffic than R12). Warp w = j-group (sW2 reads broadcast); lanes = e-groups.
// Per-output FMA order identical to R12 -> bitwise same results.
__global__ void __launch_bounds__(128) edge_kernel(const float* __restrict__ pos,
                                                   const float* __restrict__ fW1,
                                                   const float* __restrict__ fW2,
                                                   const float* __restrict__ fb2) {
    extern __shared__ float dyn[];
    float* sW2 = dyn;            // 64*64
    float* sH  = dyn + 4096;     // 64*256

    __shared__ float sXW[16 * 64];
    __shared__ float sWp[3 * 64];
    __shared__ float sB2[64];
    __shared__ int   sNbr[256];
    __shared__ float sPq[48];

    int t = threadIdx.x, q0 = blockIdx.x * 16;

    for (int idx = t * 4; idx < 4096; idx += 512)
        *(float4*)&sW2[idx] = *(const float4*)&fW2[idx];
    for (int idx = t; idx < 1024; idx += 128)
        sXW[idx] = g_xw[(size_t)q0 * DH + idx];
    for (int idx = t; idx < 192; idx += 128)
        sWp[idx] = fW1[32 * 64 + idx];               // rows 32..34 (pos part)
    for (int idx = t; idx < 256; idx += 128)
        sNbr[idx] = g_nbr[q0 * KNN + idx];
    if (t < 64) sB2[t] = fb2[t];
    if (t < 48) sPq[t] = pos[q0 * 3 + t];
    __syncthreads();

    // phase 1: sH[i][e] = relu(xw[q][i] + dpos . Wp[:,i]); thread does edges t, t+128
#pragma unroll
    for (int half = 0; half < 2; ++half) {
        int e = t + half * 128;
        int ql = e >> 4;
        int nbr = sNbr[e];
        float dx = sPq[ql * 3 + 0] - pos[nbr * 3 + 0];
        float dy = sPq[ql * 3 + 1] - pos[nbr * 3 + 1];
        float dz = sPq[ql * 3 + 2] - pos[nbr * 3 + 2];
#pragma unroll
        for (int i = 0; i < 64; i += 4) {
            float4 xw = *(float4*)&sXW[ql * 64 + i];
            float4 w0 = *(float4*)&sWp[0 * 64 + i];
            float4 w1 = *(float4*)&sWp[1 * 64 + i];
            float4 w2 = *(float4*)&sWp[2 * 64 + i];
            sH[(i + 0) * 256 + e] = fmaxf(fmaf(dz, w2.x, fmaf(dy, w1.x, fmaf(dx, w0.x, xw.x))), 0.f);
            sH[(i + 1) * 256 + e] = fmaxf(fmaf(dz, w2.y, fmaf(dy, w1.y, fmaf(dx, w0.y, xw.y))), 0.f);
            sH[(i + 2) * 256 + e] = fmaxf(fmaf(dz, w2.z, fmaf(dy, w1.z, fmaf(dx, w0.z, xw.z))), 0.f);
            sH[(i + 3) * 256 + e] = fmaxf(fmaf(dz, w2.w, fmaf(dy, w1.w, fmaf(dx, w0.w, xw.w))), 0.f);
        }
    }
    __syncthreads();

    // phase 2: h2 = relu(h1 @ W2 + b2) via FFMA2; tile = 8 edges x 16 j
    int e0 = (t & 31) * 8;      // lanes = e-groups (32 x 8 = 256 edges)
    int j0 = (t >> 5) * 16;     // warp  = j-group  (4 x 16 = 64 j) -> sW2 broadcast
    u64 acc2[8][8];
#pragma unroll
    for (int r = 0; r < 8; ++r)
#pragma unroll
        for (int c = 0; c < 8; ++c) acc2[r][c] = 0ull;

#pragma unroll 4
    for (int i = 0; i < 64; ++i) {
        float4 a0 = *(float4*)&sH[i * 256 + e0];
        float4 a1 = *(float4*)&sH[i * 256 + e0 + 4];
        ulonglong2 bb0 = *(ulonglong2*)&sW2[i * 64 + j0];
        ulonglong2 bb1 = *(ulonglong2*)&sW2[i * 64 + j0 + 4];
        ulonglong2 bb2 = *(ulonglong2*)&sW2[i * 64 + j0 + 8];
        ulonglong2 bb3 = *(ulonglong2*)&sW2[i * 64 + j0 + 12];
        u64 b2v[8] = {bb0.x, bb0.y, bb1.x, bb1.y, bb2.x, bb2.y, bb3.x, bb3.y};
        u64 ar[8] = {pack_dup(a0.x), pack_dup(a0.y), pack_dup(a0.z), pack_dup(a0.w),
                     pack_dup(a1.x), pack_dup(a1.y), pack_dup(a1.z), pack_dup(a1.w)};
#pragma unroll
        for (int r = 0; r < 8; ++r)
#pragma unroll
            for (int c = 0; c < 8; ++c) fma2(acc2[r][c], ar[r], b2v[c]);
    }

#pragma unroll
    for (int r = 0; r < 8; ++r) {
        int nbr = sNbr[e0 + r];
        int* dst = (int*)&g_agg[(size_t)nbr * DH + j0];
#pragma unroll
        for (int c = 0; c < 8; ++c) {
            float2 v = unpack2(acc2[r][c]);
            float va = fmaxf(v.x + sB2[j0 + 2 * c + 0], 0.f);
            float vb = fmaxf(v.y + sB2[j0 + 2 * c + 1], 0.f);
            if (va > 0.f) atomicMax(&dst[2 * c + 0], __float_as_int(va));
            if (vb > 0.f) atomicMax(&dst[2 * c + 1], __float_as_int(vb));
        }
    }
}

// ---------------- K4: out = relu(agg @ gW + gb) (FFMA2) ----------------
__global__ void __launch_bounds__(256) out_kernel(const float* __restrict__ gW,
                                                  const float* __restrict__ gb,
                                                  float* __restrict__ out) {
    __shared__ float sA[64 * 64];    // [i][n]
    __shared__ float sW[64 * 128];   // [i][j]
    __shared__ float sB[128];
    int t = threadIdx.x, nb = blockIdx.x * 64;
    {
        int n = t & 63, ih = (t >> 6) * 16;
        const float4* ar = (const float4*)(g_agg + (size_t)(nb + n) * DH + ih);
#pragma unroll
        for (int c4 = 0; c4 < 4; ++c4) {
            float4 v = ar[c4]; int i = ih + c4 * 4;
            sA[(i + 0) * 64 + n] = v.x; sA[(i + 1) * 64 + n] = v.y;
            sA[(i + 2) * 64 + n] = v.z; sA[(i + 3) * 64 + n] = v.w;
        }
    }
    for (int idx = t * 4; idx < 8192; idx += 1024)
        *(float4*)&sW[idx] = *(const float4*)&gW[idx];
    if (t < 128) sB[t] = gb[t];
    __syncthreads();

    int n0 = (t & 15) * 4, j0 = (t >> 4) * 8;
    u64 acc2[4][4];
#pragma unroll
    for (int r = 0; r < 4; ++r)
#pragma unroll
        for (int c = 0; c < 4; ++c) acc2[r][c] = 0ull;
#pragma unroll
    for (int i = 0; i < 64; ++i) {
        float4 a = *(float4*)&sA[i * 64 + n0];
        ulonglong2 bb0 = *(ulonglong2*)&sW[i * 128 + j0];
        ulonglong2 bb1 = *(ulonglong2*)&sW[i * 128 + j0 + 4];
        u64 b2[4] = {bb0.x, bb0.y, bb1.x, bb1.y};
        u64 ar[4] = {pack_dup(a.x), pack_dup(a.y), pack_dup(a.z), pack_dup(a.w)};
#pragma unroll
        for (int r = 0; r < 4; ++r)
#pragma unroll
            for (int c = 0; c < 4; ++c) fma2(acc2[r][c], ar[r], b2[c]);
    }
#pragma unroll
    for (int r = 0; r < 4; ++r) {
        int n = nb + n0 + r;
        float2 v0 = unpack2(acc2[r][0]), v1 = unpack2(acc2[r][1]);
        float2 v2 = unpack2(acc2[r][2]), v3 = unpack2(acc2[r][3]);
        float4 o0 = make_float4(fmaxf(v0.x + sB[j0 + 0], 0.f), fmaxf(v0.y + sB[j0 + 1], 0.f),
                                fmaxf(v1.x + sB[j0 + 2], 0.f), fmaxf(v1.y + sB[j0 + 3], 0.f));
        float4 o1 = make_float4(fmaxf(v2.x + sB[j0 + 4], 0.f), fmaxf(v2.y + sB[j0 + 5], 0.f),
                                fmaxf(v3.x + sB[j0 + 6], 0.f), fmaxf(v3.y + sB[j0 + 7], 0.f));
        *(float4*)&out[(size_t)n * DOUT + j0]     = o0;
        *(float4*)&out[(size_t)n * DOUT + j0 + 4] = o1;
    }
}

// ---------------- K5: append pos (+ batch as float) if tuple flattened ----------------
__global__ void __launch_bounds__(256) tail_kernel(const float* __restrict__ pos,
                                                   float* __restrict__ out,
                                                   int out_size) {
    int idx = blockIdx.x * blockDim.x + threadIdx.x;
    const int base = NTOT * DOUT;
    int pos_n = NTOT * 3;
    if (out_size >= base + pos_n && idx < pos_n)
        out[base + idx] = pos[idx];
    if (out_size >= base + pos_n + NTOT && idx < NTOT)
        out[base + pos_n + idx] = (float)(idx / NPER);
}

extern "C" void kernel_launch(void* const* d_in, const int* in_sizes, int n_in,
                              void* d_out, int out_size) {
    const float* x    = (const float*)d_in[0];
    const float* pos  = (const float*)d_in[1];
    // d_in[2] = batch (int32): deterministic repeat(arange(B), NPER)
    const float* fW1  = (const float*)d_in[3];
    const float* fb1  = (const float*)d_in[4];
    const float* fW2  = (const float*)d_in[5];
    const float* fb2  = (const float*)d_in[6];
    const float* gW   = (const float*)d_in[7];
    const float* gb   = (const float*)d_in[8];
    float* out = (float*)d_out;

    const int EDGE_SMEM = (4096 + 64 * 256) * sizeof(float);   // 80KB dynamic
    static int smem_set = 0;
    if (!smem_set) {
        cudaFuncSetAttribute(edge_kernel,
                             cudaFuncAttributeMaxDynamicSharedMemorySize, EDGE_SMEM);
        smem_set = 1;
    }

    knn_kernel<<<128, 256>>>(pos);
    xw_kernel<<<256, 256>>>(x, fW1, fb1);
    edge_kernel<<<2048, 128, EDGE_SMEM>>>(pos, fW1, fW2, fb2);
    out_kernel<<<512, 256>>>(gW, gb, out);
    if (out_size > NTOT * DOUT)
        tail_kernel<<<512, 256>>>(pos, out, out_size);
}

// round 15
// speedup vs baseline: 1.6566x; 1.1497x over previous
#include <cuda_runtime.h>
#include <cstdint>

#define NB      8
#define NPER    4096
#define NTOT    32768
#define KNN     16
#define DIN     32
#define DH      64
#define DOUT    128

typedef unsigned long long u64;

// ---------------- device scratch ----------------
static __device__ int   g_nbr[NTOT * KNN];
static __device__ float g_xw [NTOT * DH];
static __device__ float g_agg[NTOT * DH];

// ---------------- exact-arithmetic helpers (match XLA fp32) ----------------
__device__ __forceinline__ float sq3_exact(float x, float y, float z) {
    return __fadd_rn(__fadd_rn(__fmul_rn(x, x), __fmul_rn(y, y)), __fmul_rn(z, z));
}

// ---------------- packed fp32x2 ops (per-element rn => bitwise scalar-equal) ----------
__device__ __forceinline__ void fma2(u64& acc, u64 a2, u64 b2) {
    asm("fma.rn.f32x2 %0, %1, %2, %0;" : "+l"(acc) : "l"(a2), "l"(b2));
}
__device__ __forceinline__ u64 fma2v(u64 a, u64 b, u64 c) {
    u64 r; asm("fma.rn.f32x2 %0, %1, %2, %3;" : "=l"(r) : "l"(a), "l"(b), "l"(c)); return r;
}
__device__ __forceinline__ u64 mul2(u64 a, u64 b) {
    u64 r; asm("mul.rn.f32x2 %0, %1, %2;" : "=l"(r) : "l"(a), "l"(b)); return r;
}
__device__ __forceinline__ u64 add2(u64 a, u64 b) {
    u64 r; asm("add.rn.f32x2 %0, %1, %2;" : "=l"(r) : "l"(a), "l"(b)); return r;
}
__device__ __forceinline__ u64 pack_dup(float a) {
    u64 v; asm("mov.b64 %0, {%1, %1};" : "=l"(v) : "f"(a)); return v;
}
__device__ __forceinline__ float2 unpack2(u64 v) {
    float2 f; asm("mov.b64 {%0, %1}, %2;" : "=f"(f.x), "=f"(f.y) : "l"(v)); return f;
}

// float bits -> order-preserving unsigned
__device__ __forceinline__ unsigned int ordbits(unsigned int b) {
    return (b & 0x80000000u) ? ~b : (b | 0x80000000u);
}

// sorted-ascending insert of packed (dist,idx) key into 16-deep register list
__device__ __forceinline__ void insk16(u64 k, u64 (&K)[16]) {
#pragma unroll
    for (int s = 0; s < 16; ++s) {
        bool p = k < K[s];
        u64 lo = p ? k : K[s];
        u64 hi = p ? K[s] : k;
        K[s] = lo; k = hi;
    }
}

// ---------------- fillers: position knn_kernel as the 4th launch for ncu ----------------
__global__ void filler_kernel() {}

// ---------------- K1: brute-force KNN, branch-free append + FFMA2 pair distances ------
// Per-candidate math now packed 2-wide:
//   dot2 = fma2(qz,cz, fma2(qy,cy, mul2(qx,cx)))           (same order as scalar)
//   d2   = add2(qsq+csq, mul2(-2, dot2))                   (rn sign-symmetric =>
//          bitwise == __fsub_rn(add, __fmul_rn(2, dot)))
// Append machinery identical to R12 (branch-free store, predicated cnt, vote drain).
#define KBUF 15
__global__ void __launch_bounds__(256) knn_kernel(const float* __restrict__ pos) {
    __shared__ float sx[1024], sy[1024], sz[1024], ssq[1024];   // SoA candidates 16KB
    __shared__ uint2 sbuf[256 * KBUF];                          // append buffers 30KB

    int graph = blockIdx.x >> 4;
    int q     = graph * NPER + (blockIdx.x & 15) * 256 + threadIdx.x;
    int cbase = graph * NPER;

    float qx = pos[q * 3 + 0], qy = pos[q * 3 + 1], qz = pos[q * 3 + 2];
    float qsq = sq3_exact(qx, qy, qz);
    u64 qx2 = pack_dup(qx), qy2 = pack_dup(qy), qz2 = pack_dup(qz);
    u64 qs2 = pack_dup(qsq), n2 = pack_dup(-2.0f);

    u64 K[16];
#pragma unroll
    for (int s = 0; s < 16; ++s) K[s] = ~0ull;
    float worstd = __int_as_float(0x7f800000);   // +inf -> append-all until full
    int cnt = 0;
    uint2* mybuf = &sbuf[threadIdx.x * KBUF];

#pragma unroll 1
    for (int chunk = 0; chunk < 4; ++chunk) {
#pragma unroll
        for (int u = 0; u < 4; ++u) {
            int li = threadIdx.x + u * 256;
            int gi = cbase + chunk * 1024 + li;
            float x = pos[gi * 3 + 0], y = pos[gi * 3 + 1], z = pos[gi * 3 + 2];
            sx[li] = x; sy[li] = y; sz[li] = z; ssq[li] = sq3_exact(x, y, z);
        }
        __syncthreads();

#pragma unroll 1
        for (int j = 0; j < 1024; j += 8) {
#pragma unroll
            for (int p = 0; p < 4; ++p) {
                int c0 = j + p * 2;                          // 8B-aligned (even)
                u64 cx2 = *(const u64*)&sx[c0];              // broadcast LDS.64
                u64 cy2 = *(const u64*)&sy[c0];
                u64 cz2 = *(const u64*)&sz[c0];
                u64 cs2 = *(const u64*)&ssq[c0];
                u64 dot2 = fma2v(qz2, cz2, fma2v(qy2, cy2, mul2(qx2, cx2)));
                u64 d2   = add2(add2(qs2, cs2), mul2(n2, dot2));
                float2 d = unpack2(d2);
                // branch-free appends, ascending candidate index order
                mybuf[cnt] = make_uint2(__float_as_uint(d.x),
                                        (unsigned)(chunk * 1024 + c0));
                cnt += !(d.x > worstd) ? 1 : 0;              // NaN/inf worstd -> take
                mybuf[cnt] = make_uint2(__float_as_uint(d.y),
                                        (unsigned)(chunk * 1024 + c0 + 1));
                cnt += !(d.y > worstd) ? 1 : 0;
            }
            if (__any_sync(0xffffffffu, cnt >= KBUF - 8)) {   // warp-uniform
                for (int k = 0; k < cnt; ++k) {
                    uint2 e = mybuf[k];
                    u64 key = ((u64)ordbits(e.x) << 16) | e.y;
                    if (key < K[15]) insk16(key, K);
                }
                cnt = 0;
                unsigned int o = (unsigned int)(K[15] >> 16);
                unsigned int b = (o & 0x80000000u) ? (o & 0x7FFFFFFFu) : ~o;
                worstd = __uint_as_float(b);     // NaN while list not full (safe)
            }
        }
        __syncthreads();
    }

    for (int k = 0; k < cnt; ++k) {
        uint2 e = mybuf[k];
        u64 key = ((u64)ordbits(e.x) << 16) | e.y;
        if (key < K[15]) insk16(key, K);
    }

#pragma unroll
    for (int s = 0; s < 16; ++s)
        g_nbr[q * KNN + s] = cbase + (int)(K[s] & 0xFFFFull);
}

// ---------------- K2: xw = x @ fW1[0:32,:] + fb1 ; zero g_agg (FFMA2) ----------------
__global__ void __launch_bounds__(256) xw_kernel(const float* __restrict__ x,
                                                 const float* __restrict__ fW1,
                                                 const float* __restrict__ fb1) {
    __shared__ float sX[32 * 128];   // [i][n]
    __shared__ float sW[32 * 64];    // [i][j]
    __shared__ float sB[64];
    int t = threadIdx.x, nb = blockIdx.x * 128;
    {
        int n = t & 127, ih = (t >> 7) * 16;
        const float4* xr = (const float4*)(x + (size_t)(nb + n) * DIN + ih);
#pragma unroll
        for (int c4 = 0; c4 < 4; ++c4) {
            float4 v = xr[c4]; int i = ih + c4 * 4;
            sX[(i + 0) * 128 + n] = v.x; sX[(i + 1) * 128 + n] = v.y;
            sX[(i + 2) * 128 + n] = v.z; sX[(i + 3) * 128 + n] = v.w;
        }
    }
    for (int idx = t * 4; idx < 2048; idx += 1024)
        *(float4*)&sW[idx] = *(const float4*)&fW1[idx];
    if (t < 64) sB[t] = fb1[t];
    __syncthreads();

    int n0 = (t & 31) * 4, j0 = (t >> 5) * 8;
    u64 acc2[4][4];
#pragma unroll
    for (int r = 0; r < 4; ++r)
#pragma unroll
        for (int c = 0; c < 4; ++c) acc2[r][c] = 0ull;
#pragma unroll
    for (int i = 0; i < 32; ++i) {
        float4 a = *(float4*)&sX[i * 128 + n0];
        ulonglong2 bb0 = *(ulonglong2*)&sW[i * 64 + j0];
        ulonglong2 bb1 = *(ulonglong2*)&sW[i * 64 + j0 + 4];
        u64 b2[4] = {bb0.x, bb0.y, bb1.x, bb1.y};
        u64 ar[4] = {pack_dup(a.x), pack_dup(a.y), pack_dup(a.z), pack_dup(a.w)};
#pragma unroll
        for (int r = 0; r < 4; ++r)
#pragma unroll
            for (int c = 0; c < 4; ++c) fma2(acc2[r][c], ar[r], b2[c]);
    }
#pragma unroll
    for (int r = 0; r < 4; ++r) {
        int n = nb + n0 + r;
        float2 v0 = unpack2(acc2[r][0]), v1 = unpack2(acc2[r][1]);
        float2 v2 = unpack2(acc2[r][2]), v3 = unpack2(acc2[r][3]);
        float4 o0 = make_float4(v0.x + sB[j0 + 0], v0.y + sB[j0 + 1],
                                v1.x + sB[j0 + 2], v1.y + sB[j0 + 3]);
        float4 o1 = make_float4(v2.x + sB[j0 + 4], v2.y + sB[j0 + 5],
                                v3.x + sB[j0 + 6], v3.y + sB[j0 + 7]);
        *(float4*)&g_xw[(size_t)n * DH + j0]     = o0;
        *(float4*)&g_xw[(size_t)n * DH + j0 + 4] = o1;
        float4 z4 = make_float4(0.f, 0.f, 0.f, 0.f);
        *(float4*)&g_agg[(size_t)n * DH + j0]     = z4;
        *(float4*)&g_agg[(size_t)n * DH + j0 + 4] = z4;
    }
}

// ---------------- K3: edge MLP + atomic segment max (R12 exact: 4q/64e, 128 thr) ------
__global__ void __launch_bounds__(128) edge_kernel(const float* __restrict__ pos,
                                                   const float* __restrict__ fW1,
                                                   const float* __restrict__ fW2,
                                                   const float* __restrict__ fb2) {
    __shared__ float sW2[64 * 64];   // [i][j]
    __shared__ float sH [64 * 64];   // [i][e]
    __shared__ float sXW[4 * 64];
    __shared__ float sWp[3 * 64];
    __shared__ float sB2[64];
    __shared__ int   sNbr[64];
    __shared__ float sPq[12];

    int t = threadIdx.x, q0 = blockIdx.x * 4;
    for (int idx = t * 4; idx < 4096; idx += 512)
        *(float4*)&sW2[idx] = *(const float4*)&fW2[idx];
    for (int idx = t; idx < 256; idx += 128)
        sXW[idx] = g_xw[(size_t)q0 * DH + idx];
    for (int idx = t; idx < 192; idx += 128)
        sWp[idx] = fW1[32 * 64 + idx];               // rows 32..34 (pos part)
    if (t < 64)  { sB2[t] = fb2[t]; sNbr[t] = g_nbr[q0 * KNN + t]; }
    if (t < 12)  sPq[t] = pos[q0 * 3 + t];
    __syncthreads();

    // phase 1: sH[i][e] = relu(xw[q][i] + dpos . Wp[:,i])
    {
        int e = t & 63, i0 = (t >> 6) * 32, ql = e >> 4;
        int nbr = sNbr[e];
        float dx = sPq[ql * 3 + 0] - pos[nbr * 3 + 0];
        float dy = sPq[ql * 3 + 1] - pos[nbr * 3 + 1];
        float dz = sPq[ql * 3 + 2] - pos[nbr * 3 + 2];
#pragma unroll
        for (int ib = 0; ib < 32; ib += 4) {
            int i = i0 + ib;
            float4 xw = *(float4*)&sXW[ql * 64 + i];
            float4 w0 = *(float4*)&sWp[0 * 64 + i];
            float4 w1 = *(float4*)&sWp[1 * 64 + i];
            float4 w2 = *(float4*)&sWp[2 * 64 + i];
            sH[(i + 0) * 64 + e] = fmaxf(fmaf(dz, w2.x, fmaf(dy, w1.x, fmaf(dx, w0.x, xw.x))), 0.f);
            sH[(i + 1) * 64 + e] = fmaxf(fmaf(dz, w2.y, fmaf(dy, w1.y, fmaf(dx, w0.y, xw.y))), 0.f);
            sH[(i + 2) * 64 + e] = fmaxf(fmaf(dz, w2.z, fmaf(dy, w1.z, fmaf(dx, w0.z, xw.z))), 0.f);
            sH[(i + 3) * 64 + e] = fmaxf(fmaf(dz, w2.w, fmaf(dy, w1.w, fmaf(dx, w0.w, xw.w))), 0.f);
        }
    }
    __syncthreads();

    // phase 2: h2 = relu(h1 @ W2 + b2) via FFMA2, atomicMax into g_agg[nbr]
    int e0 = (t & 15) * 4, j0 = (t >> 4) * 8;
    u64 acc2[4][4];
#pragma unroll
    for (int r = 0; r < 4; ++r)
#pragma unroll
        for (int c = 0; c < 4; ++c) acc2[r][c] = 0ull;
#pragma unroll
    for (int i = 0; i < 64; ++i) {
        float4 a = *(float4*)&sH[i * 64 + e0];
        ulonglong2 bb0 = *(ulonglong2*)&sW2[i * 64 + j0];
        ulonglong2 bb1 = *(ulonglong2*)&sW2[i * 64 + j0 + 4];
        u64 b2[4] = {bb0.x, bb0.y, bb1.x, bb1.y};
        u64 ar[4] = {pack_dup(a.x), pack_dup(a.y), pack_dup(a.z), pack_dup(a.w)};
#pragma unroll
        for (int r = 0; r < 4; ++r)
#pragma unroll
            for (int c = 0; c < 4; ++c) fma2(acc2[r][c], ar[r], b2[c]);
    }
#pragma unroll
    for (int r = 0; r < 4; ++r) {
        int nbr = sNbr[e0 + r];
        int* dst = (int*)&g_agg[(size_t)nbr * DH + j0];
#pragma unroll
        for (int c = 0; c < 4; ++c) {
            float2 v = unpack2(acc2[r][c]);
            float va = fmaxf(v.x + sB2[j0 + 2 * c + 0], 0.f);
            float vb = fmaxf(v.y + sB2[j0 + 2 * c + 1], 0.f);
            if (va > 0.f) atomicMax(&dst[2 * c + 0], __float_as_int(va));
            if (vb > 0.f) atomicMax(&dst[2 * c + 1], __float_as_int(vb));
        }
    }
}

// ---------------- K4: out = relu(agg @ gW + gb) (FFMA2) ----------------
__global__ void __launch_bounds__(256) out_kernel(const float* __restrict__ gW,
                                                  const float* __restrict__ gb,
                                                  float* __restrict__ out) {
    __shared__ float sA[64 * 64];    // [i][n]
    __shared__ float sW[64 * 128];   // [i][j]
    __shared__ float sB[128];
    int t = threadIdx.x, nb = blockIdx.x * 64;
    {
        int n = t & 63, ih = (t >> 6) * 16;
        const float4* ar = (const float4*)(g_agg + (size_t)(nb + n) * DH + ih);
#pragma unroll
        for (int c4 = 0; c4 < 4; ++c4) {
            float4 v = ar[c4]; int i = ih + c4 * 4;
            sA[(i + 0) * 64 + n] = v.x; sA[(i + 1) * 64 + n] = v.y;
            sA[(i + 2) * 64 + n] = v.z; sA[(i + 3) * 64 + n] = v.w;
        }
    }
    for (int idx = t * 4; idx < 8192; idx += 1024)
        *(float4*)&sW[idx] = *(const float4*)&gW[idx];
    if (t < 128) sB[t] = gb[t];
    __syncthreads();

    int n0 = (t & 15) * 4, j0 = (t >> 4) * 8;
    u64 acc2[4][4];
#pragma unroll
    for (int r = 0; r < 4; ++r)
#pragma unroll
        for (int c = 0; c < 4; ++c) acc2[r][c] = 0ull;
#pragma unroll
    for (int i = 0; i < 64; ++i) {
        float4 a = *(float4*)&sA[i * 64 + n0];
        ulonglong2 bb0 = *(ulonglong2*)&sW[i * 128 + j0];
        ulonglong2 bb1 = *(ulonglong2*)&sW[i * 128 + j0 + 4];
        u64 b2[4] = {bb0.x, bb0.y, bb1.x, bb1.y};
        u64 ar[4] = {pack_dup(a.x), pack_dup(a.y), pack_dup(a.z), pack_dup(a.w)};
#pragma unroll
        for (int r = 0; r < 4; ++r)
#pragma unroll
            for (int c = 0; c < 4; ++c) fma2(acc2[r][c], ar[r], b2[c]);
    }
#pragma unroll
    for (int r = 0; r < 4; ++r) {
        int n = nb + n0 + r;
        float2 v0 = unpack2(acc2[r][0]), v1 = unpack2(acc2[r][1]);
        float2 v2 = unpack2(acc2[r][2]), v3 = unpack2(acc2[r][3]);
        float4 o0 = make_float4(fmaxf(v0.x + sB[j0 + 0], 0.f), fmaxf(v0.y + sB[j0 + 1], 0.f),
                                fmaxf(v1.x + sB[j0 + 2], 0.f), fmaxf(v1.y + sB[j0 + 3], 0.f));
        float4 o1 = make_float4(fmaxf(v2.x + sB[j0 + 4], 0.f), fmaxf(v2.y + sB[j0 + 5], 0.f),
                                fmaxf(v3.x + sB[j0 + 6], 0.f), fmaxf(v3.y + sB[j0 + 7], 0.f));
        *(float4*)&out[(size_t)n * DOUT + j0]     = o0;
        *(float4*)&out[(size_t)n * DOUT + j0 + 4] = o1;
    }
}

// ---------------- K5: append pos (+ batch as float) if tuple flattened ----------------
__global__ void __launch_bounds__(256) tail_kernel(const float* __restrict__ pos,
                                                   float* __restrict__ out,
                                                   int out_size) {
    int idx = blockIdx.x * blockDim.x + threadIdx.x;
    const int base = NTOT * DOUT;
    int pos_n = NTOT * 3;
    if (out_size >= base + pos_n && idx < pos_n)
        out[base + idx] = pos[idx];
    if (out_size >= base + pos_n + NTOT && idx < NTOT)
        out[base + pos_n + idx] = (float)(idx / NPER);
}

extern "C" void kernel_launch(void* const* d_in, const int* in_sizes, int n_in,
                              void* d_out, int out_size) {
    const float* x    = (const float*)d_in[0];
    const float* pos  = (const float*)d_in[1];
    // d_in[2] = batch (int32): deterministic repeat(arange(B), NPER)
    const float* fW1  = (const float*)d_in[3];
    const float* fb1  = (const float*)d_in[4];
    const float* fW2  = (const float*)d_in[5];
    const float* fb2  = (const float*)d_in[6];
    const float* gW   = (const float*)d_in[7];
    const float* gb   = (const float*)d_in[8];
    float* out = (float*)d_out;

    // Launch order places knn_kernel 4th (observed ncu capture slot) so the
    // profile finally lands on the dominant kernel. Dependencies preserved:
    // edge needs g_xw (launch 1) and g_nbr (launch 4).
    xw_kernel<<<256, 256>>>(x, fW1, fb1);
    filler_kernel<<<1, 32>>>();
    filler_kernel<<<1, 32>>>();
    knn_kernel<<<128, 256>>>(pos);
    edge_kernel<<<8192, 128>>>(pos, fW1, fW2, fb2);
    out_kernel<<<512, 256>>>(gW, gb, out);
    if (out_size > NTOT * DOUT)
        tail_kernel<<<512, 256>>>(pos, out, out_size);
}